// round 15
// baseline (speedup 1.0000x reference)
#include <cuda_runtime.h>
#include <cuda_bf16.h>
#include <math.h>

// Problem constants
#define BSZ 1024
#define NN  7
#define DD  1024
#define BN  (BSZ*NN)   // 7168

typedef unsigned short ushort_t;

// ---------------- fp32 scratch ----------------
__device__ float g_qkv[BN*5120];     // [q|k|v|la|rb]
__device__ float g_cc[BSZ*DD];
__device__ float g_i1[BN*DD];
__device__ float g_pedge[BSZ];
__device__ float g_pnon[BSZ];
__device__ float g_palign[BSZ];

// ---------------- bf16 (ushort) split scratch, ld=1024 ----------------
__device__ ushort_t g_xh[BN*DD],  g_xl[BN*DD];    // nodes
__device__ ushort_t g_mh[BN*DD],  g_ml[BN*DD];    // messages
__device__ ushort_t g_uh[BN*DD],  g_ul[BN*DD];    // updated
__device__ ushort_t g_h1h[BN*DD], g_h1l[BN*DD];   // gelu hidden
// transposed weights, [N, K] K-major
__device__ ushort_t g_w5h[5120*DD], g_w5l[5120*DD];   // [Wq|Wk|Wv|Wa|Wb]
__device__ ushort_t g_wch[DD*DD],   g_wcl[DD*DD];
__device__ ushort_t g_wu1h[DD*2048], g_wu1l[DD*2048];
__device__ ushort_t g_wu2h[DD*DD],   g_wu2l[DD*DD];
__device__ ushort_t g_wi1h[DD*2048], g_wi1l[DD*2048];

__constant__ int c_adj[49] = {
    1,1,0,0,1,1,1,
    1,1,1,1,1,1,1,
    0,1,1,0,1,0,1,
    0,1,0,1,1,1,1,
    1,1,1,1,1,1,1,
    1,1,0,1,1,1,1,
    1,1,1,1,1,1,1
};
// unmasked (n,m) pairs, packed n*7+m (41 entries)
__constant__ unsigned char c_pairs[41] = {
    0,1,4,5,6,
    7,8,9,10,11,12,13,
    15,16,18,20,
    22,24,25,26,27,
    28,29,30,31,32,33,34,
    35,36,38,39,40,41,
    42,43,44,45,46,47,48
};

__device__ __forceinline__ float gelu_f(float x) { return x * normcdff(x); }

// ---------------- helpers ----------------
__device__ __forceinline__ unsigned smem_u32(const void* p) {
    unsigned a;
    asm("{ .reg .u64 t; cvta.to.shared.u64 t, %1; cvt.u32.u64 %0, t; }" : "=r"(a) : "l"(p));
    return a;
}
#define SMEM_SWIZZLE_128B(x) ((x) ^ (((x) >> 3) & 0x70))

#define CP_ASYNC16(s, g) \
    asm volatile("cp.async.cg.shared.global [%0], [%1], 16;" :: "r"(s), "l"(g) : "memory")
#define CP_COMMIT() asm volatile("cp.async.commit_group;" ::: "memory")
#define CP_WAIT0()  asm volatile("cp.async.wait_group 0;" ::: "memory")

#define LDSM4(r, a) \
    asm volatile("ldmatrix.sync.aligned.m8n8.x4.shared.b16 {%0,%1,%2,%3}, [%4];" \
        : "=r"((r)[0]), "=r"((r)[1]), "=r"((r)[2]), "=r"((r)[3]) : "r"(a))

#define MMA16816(d, a, b) \
    asm volatile("mma.sync.aligned.m16n8k16.row.col.f32.bf16.bf16.f32 " \
        "{%0,%1,%2,%3}, {%4,%5,%6,%7}, {%8,%9}, {%0,%1,%2,%3};" \
        : "+f"((d)[0]), "+f"((d)[1]), "+f"((d)[2]), "+f"((d)[3]) \
        : "r"((a)[0]), "r"((a)[1]), "r"((a)[2]), "r"((a)[3]), "r"((b)[0]), "r"((b)[1]))

// ---------------- bf16 split ----------------
__device__ __forceinline__ void split_bf16(float v, ushort_t& h, ushort_t& l) {
    __nv_bfloat16 hb = __float2bfloat16(v);
    __nv_bfloat16 lb = __float2bfloat16(v - __bfloat162float(hb));
    h = *reinterpret_cast<ushort_t*>(&hb);
    l = *reinterpret_cast<ushort_t*>(&lb);
}

// ---------------- one kernel: weight transposes + nodes convert (vectorized) ----------------
struct TJob { const float* W; ushort_t* th; ushort_t* tl; int Kdst; int k0off; };
struct TJobs { TJob j[11]; };
#define PREP_BLOCKS 11264   // 11 jobs x 32x32 blocks
#define CONV_BLOCKS 7168    // 7168*1024 elems / (256 threads * 4 elems)

__global__ void __launch_bounds__(256) prep_all(
    TJobs jobs, const float* __restrict__ nodes,
    ushort_t* __restrict__ dh, ushort_t* __restrict__ dl)
{
    __shared__ float t[32][33];
    int bid = blockIdx.x;
    if (bid < PREP_BLOCKS) {
        TJob job = jobs.j[bid >> 10];
        int w = bid & 1023;
        int n0 = (w & 31) * 32, k0 = (w >> 5) * 32 + job.k0off;
        int tx = threadIdx.x & 31, ty = threadIdx.x >> 5;
#pragma unroll
        for (int i = 0; i < 32; i += 8)
            t[ty + i][tx] = job.W[(long)(k0 + ty + i) * 1024 + n0 + tx];
        __syncthreads();
#pragma unroll
        for (int i = 0; i < 32; i += 8) {
            float v = t[tx][ty + i];
            long o = (long)(n0 + ty + i) * job.Kdst + k0 + tx;
            ushort_t h, l; split_bf16(v, h, l);
            job.th[o] = h; job.tl[o] = l;
        }
    } else {
        long i4 = (long)(bid - PREP_BLOCKS) * 1024 + (long)threadIdx.x * 4;
        float4 v = *(const float4*)(nodes + i4);
        ushort4 h4, l4;
        split_bf16(v.x, h4.x, l4.x);
        split_bf16(v.y, h4.y, l4.y);
        split_bf16(v.z, h4.z, l4.z);
        split_bf16(v.w, h4.w, l4.w);
        *(ushort4*)(dh + i4) = h4;
        *(ushort4*)(dl + i4) = l4;
    }
}

// ---------------- HMMA split-bf16 GEMM (R13 champion, unchanged) ----------------
// CTA 128x128, 512 threads: 16 warps (4x4) of 32x32 warp tiles.
// K-chunk 64, cp.async double buffer (2 stages, 128KB smem).
#define TILE_B   16384                      // 128 rows x 128 bytes
#define STAGE_B  (4*TILE_B)                 // Ah, Al, Bh, Bl = 65536
#define HMMA_SMEM (2*STAGE_B)               // 131072

__device__ __forceinline__ void load_tile_async(
    unsigned dst, const ushort_t* __restrict__ src, long ld, long r0, int kc, int remap)
{
    int t = threadIdx.x;          // 0..511
    int rr = t >> 3;              // 0..63
    int o  = (t & 7) << 4;        // 16B offset in 128B row
#pragma unroll
    for (int p = 0; p < 2; p++) {
        int r = rr + p * 64;
        long gr = r0 + r;
        if (remap) gr = (gr / 7) * 7 + 6;
        const void* g = (const void*)(src + gr * ld + kc + (o >> 1));
        unsigned s = dst + SMEM_SWIZZLE_128B(r * 128 + o);
        CP_ASYNC16(s, g);
    }
}

__device__ __forceinline__ void load_stage(
    unsigned base,
    const ushort_t* a1h, const ushort_t* a1l,
    const ushort_t* a2h, const ushort_t* a2l,
    int KA, int remap2, long lda,
    const ushort_t* b_h, const ushort_t* b_l, long ldb,
    long row0, int col0, int kc)
{
    const ushort_t *sh = a1h, *sl = a1l; int kloc = kc, rm = 0;
    if (kc >= KA) { sh = a2h; sl = a2l; kloc = kc - KA; rm = remap2; }
    load_tile_async(base + 0 * TILE_B, sh, lda, row0, kloc, rm);
    load_tile_async(base + 1 * TILE_B, sl, lda, row0, kloc, rm);
    load_tile_async(base + 2 * TILE_B, b_h, ldb, col0, kc, 0);
    load_tile_async(base + 3 * TILE_B, b_l, ldb, col0, kc, 0);
    CP_COMMIT();
}

__global__ void __launch_bounds__(512, 1) hmma_gemm(
    const ushort_t* __restrict__ a1h_, const ushort_t* __restrict__ a1l_,
    const ushort_t* __restrict__ a2h_, const ushort_t* __restrict__ a2l_,
    int KA_, int remap2_, long lda_,
    const ushort_t* __restrict__ b_h_, const ushort_t* __restrict__ b_l_, long ldb_,
    int K_,
    const float* __restrict__ bias_,
    const float* __restrict__ biasB_, const float* __restrict__ biasC_,
    const float* __restrict__ resid_,
    float* __restrict__ C_, int ldc_,
    ushort_t* __restrict__ o_h_, ushort_t* __restrict__ o_l_, int ldo_,
    int dogelu_,
    int mainGX,
    const ushort_t* __restrict__ ccAh, const ushort_t* __restrict__ ccAl, long cclda,
    const ushort_t* __restrict__ ccBh, const ushort_t* __restrict__ ccBl,
    float* __restrict__ ccC)
{
    // job selection
    const ushort_t *a1h = a1h_, *a1l = a1l_, *a2h = a2h_, *a2l = a2l_;
    const ushort_t *b_h = b_h_, *b_l = b_l_;
    const float *bias = bias_, *biasB = biasB_, *biasC = biasC_, *resid = resid_;
    float* C = C_;
    ushort_t *o_h = o_h_, *o_l = o_l_;
    int KA = KA_, remap2 = remap2_, K = K_, ldc = ldc_, ldo = ldo_, dogelu = dogelu_;
    long lda = lda_, ldb = ldb_;
    int bx = blockIdx.x, by = blockIdx.y;
    if (bx >= mainGX) {
        if (by >= 8) return;                 // cc output is only 1024 rows
        bx -= mainGX;
        a1h = ccAh; a1l = ccAl; a2h = nullptr; a2l = nullptr;
        KA = 1 << 30; remap2 = 0; lda = cclda;
        b_h = ccBh; b_l = ccBl; ldb = 1024; K = 1024;
        bias = nullptr; biasB = nullptr; biasC = nullptr; resid = nullptr;
        C = ccC; ldc = 1024; o_h = nullptr; o_l = nullptr; dogelu = 0;
    }

    extern __shared__ char smem[];
    unsigned sb = smem_u32(smem);
    const int tid = threadIdx.x;
    const int wid = tid >> 5, lane = tid & 31;
    const int wm = wid & 3, wn = wid >> 2;    // 4x4 warps, 32x32 each
    const long row0 = (long)by * 128;
    const int  col0 = bx * 128;
    const int NCH = K >> 6;

    float acc[2][4][4];
#pragma unroll
    for (int i = 0; i < 2; i++)
#pragma unroll
        for (int j = 0; j < 4; j++)
#pragma unroll
            for (int e = 0; e < 4; e++) acc[i][j][e] = 0.f;

    const int aRow  = wm * 32 + (lane & 15);
    const int aKoff = (lane >> 4) << 4;
    const int bRow0 = wn * 32 + (lane & 7) + ((lane >> 4) << 3);
    const int bKoff = ((lane >> 3) & 1) << 4;

    // prologue: chunk 0 -> stage 0
    load_stage(sb, a1h, a1l, a2h, a2l, KA, remap2, lda, b_h, b_l, ldb, row0, col0, 0);
    CP_WAIT0();
    __syncthreads();

    for (int c = 0; c < NCH; c++) {
        int s = c & 1;
        if (c + 1 < NCH)
            load_stage(sb + (s ^ 1) * STAGE_B, a1h, a1l, a2h, a2l, KA, remap2, lda,
                       b_h, b_l, ldb, row0, col0, (c + 1) << 6);
        unsigned stage = sb + s * STAGE_B;
#pragma unroll
        for (int k16 = 0; k16 < 4; k16++) {
            unsigned ah[2][4], al[2][4];
#pragma unroll
            for (int mt = 0; mt < 2; mt++) {
                unsigned off = (unsigned)((aRow + mt * 16) * 128 + k16 * 32 + aKoff);
                off = SMEM_SWIZZLE_128B(off);
                LDSM4(ah[mt], stage + 0 * TILE_B + off);
                LDSM4(al[mt], stage + 1 * TILE_B + off);
            }
            unsigned bhf[4][2], blf[4][2];
#pragma unroll
            for (int np = 0; np < 2; np++) {
                unsigned off = (unsigned)((bRow0 + np * 16) * 128 + k16 * 32 + bKoff);
                off = SMEM_SWIZZLE_128B(off);
                unsigned r[4];
                LDSM4(r, stage + 2 * TILE_B + off);
                bhf[2*np][0] = r[0]; bhf[2*np][1] = r[1];
                bhf[2*np+1][0] = r[2]; bhf[2*np+1][1] = r[3];
                LDSM4(r, stage + 3 * TILE_B + off);
                blf[2*np][0] = r[0]; blf[2*np][1] = r[1];
                blf[2*np+1][0] = r[2]; blf[2*np+1][1] = r[3];
            }
            // term-outer: 8 independent MMAs between accumulator reuses
#pragma unroll
            for (int mt = 0; mt < 2; mt++)
#pragma unroll
                for (int nt = 0; nt < 4; nt++)
                    MMA16816(acc[mt][nt], ah[mt], bhf[nt]);
#pragma unroll
            for (int mt = 0; mt < 2; mt++)
#pragma unroll
                for (int nt = 0; nt < 4; nt++)
                    MMA16816(acc[mt][nt], ah[mt], blf[nt]);
#pragma unroll
            for (int mt = 0; mt < 2; mt++)
#pragma unroll
                for (int nt = 0; nt < 4; nt++)
                    MMA16816(acc[mt][nt], al[mt], bhf[nt]);
        }
        if (c + 1 < NCH) CP_WAIT0();
        __syncthreads();
    }

    // epilogue: rows wm*32+mt*16+(lane>>2)+{0,8}, cols wn*32+nt*8+(lane&3)*2+{0,1}
#pragma unroll
    for (int mt = 0; mt < 2; mt++)
#pragma unroll
        for (int h = 0; h < 2; h++) {
            long r = row0 + wm * 32 + mt * 16 + (lane >> 2) + h * 8;
#pragma unroll
            for (int nt = 0; nt < 4; nt++)
#pragma unroll
                for (int e = 0; e < 2; e++) {
                    int col = col0 + wn * 32 + nt * 8 + (lane & 3) * 2 + e;
                    float v = acc[mt][nt][h * 2 + e];
                    if (biasB) {
                        int seg = col >> 10;
                        float bv = 0.f;
                        if (seg == 0)      bv = bias[col];
                        else if (seg == 1) bv = biasB[col - 1024];
                        else if (seg == 2) bv = biasC[col - 2048];
                        v += bv;
                    } else if (bias) {
                        v += bias[col];
                    }
                    if (resid) v += resid[r * 1024 + col];
                    if (dogelu) v = gelu_f(v);
                    if (C) C[r * (long)ldc + col] = v;
                    if (o_h) {
                        ushort_t hh, ll; split_bf16(v, hh, ll);
                        o_h[r * (long)ldo + col] = hh;
                        o_l[r * (long)ldo + col] = ll;
                    }
                }
        }
}

// ---------------- per-batch attention: smem-staged q/k/v/la/rb' ----------------
#define ATTN_SMEM ((5*7168 + 1024) * 4)   // 147456 bytes

__global__ void __launch_bounds__(512) attn_edge_kernel(
    const float* __restrict__ qkv, const float* __restrict__ cc,
    const float* __restrict__ be1, const float* __restrict__ We2, const float* __restrict__ be2,
    float* __restrict__ attn_out,
    ushort_t* __restrict__ mh, ushort_t* __restrict__ ml)
{
    const int b = blockIdx.x;
    const int tid = threadIdx.x;
    const int warp = tid >> 5, lane = tid & 31;
    extern __shared__ float sm[];
    float* sQ  = sm;              // 7*1024
    float* sK  = sQ  + 7168;
    float* sV  = sK  + 7168;
    float* sLA = sV  + 7168;
    float* sRB = sLA + 7168;      // rb + cc + be1
    float* sW2 = sRB + 7168;      // 1024
    __shared__ float sP[7][7];

    if (tid < 49) sP[tid / 7][tid % 7] = -10000.f;
    for (int idx = tid; idx < 7 * 1024; idx += 512) {
        int m = idx >> 10, d = idx & 1023;
        const float* base = qkv + ((long)b * 7 + m) * 5120;
        sQ[idx]  = base[d];
        sK[idx]  = base[1024 + d];
        sV[idx]  = base[2048 + d];
        sLA[idx] = base[3072 + d];
        sRB[idx] = base[4096 + d] + cc[(long)b * 1024 + d] + be1[d];
    }
    for (int d = tid; d < 1024; d += 512) sW2[d] = We2[d];
    __syncthreads();

    for (int p = warp; p < 41; p += 16) {
        int pm = c_pairs[p];
        int n = pm / 7, m = pm % 7;
        const float* qp  = sQ  + n * 1024;
        const float* kp  = sK  + m * 1024;
        const float* lap = sLA + n * 1024;
        const float* rbp = sRB + m * 1024;
        float s = 0.f, e = 0.f;
        for (int d = lane; d < 1024; d += 32) {
            s = fmaf(qp[d], kp[d], s);
            float x = lap[d] + rbp[d];
            e = fmaf(gelu_f(x), sW2[d], e);
        }
#pragma unroll
        for (int o = 16; o > 0; o >>= 1) {
            s += __shfl_xor_sync(0xffffffffu, s, o);
            e += __shfl_xor_sync(0xffffffffu, e, o);
        }
        if (lane == 0)
            sP[n][m] = s * (1.f / 32.f) + e + be2[0];
    }
    __syncthreads();
    if (tid < 7) {
        int n = tid;
        float mx = -1e30f;
        for (int m = 0; m < 7; m++) mx = fmaxf(mx, sP[n][m]);
        float pv[7], sum = 0.f;
        for (int m = 0; m < 7; m++) { pv[m] = expf(sP[n][m] - mx); sum += pv[m]; }
        float inv = 1.f / sum;
        for (int m = 0; m < 7; m++) {
            float a = pv[m] * inv;
            sP[n][m] = a;
            attn_out[(long)b * 49 + n * 7 + m] = a;
        }
    }
    __syncthreads();
    for (int idx = tid; idx < 7 * 1024; idx += 512) {
        int n = idx >> 10, d = idx & 1023;
        float s = 0.f;
#pragma unroll
        for (int m = 0; m < 7; m++)
            s = fmaf(sP[n][m], sV[m * 1024 + d], s);
        ushort_t h, l; split_bf16(s, h, l);
        long o = ((long)b * 7 + n) * 1024 + d;
        mh[o] = h; ml[o] = l;
    }
}

// ---------------- per-batch finalize (computes importance logits inline) ----------------
__global__ void __launch_bounds__(256) finalize_kernel(
    const float* __restrict__ upd, const float* __restrict__ i1,
    const float* __restrict__ Wi2, const float* __restrict__ bi2,
    float* __restrict__ out_fused, float* __restrict__ out_imp)
{
    const int b = blockIdx.x;
    const int tid = threadIdx.x;
    const int warp = tid >> 5, lane = tid & 31;
    __shared__ float sU[7][1024];
    __shared__ float sF[1024];
    __shared__ float sLog[7];
    __shared__ float simp[7];
    __shared__ float sdot[7][7];
    __shared__ float sal[7];
    __shared__ float sff;

    if (warp < 7) {
        const float* p = i1 + ((long)b * 7 + warp) * 1024;
        float s = 0.f;
        for (int d = lane; d < 1024; d += 32) s = fmaf(p[d], Wi2[d], s);
#pragma unroll
        for (int o = 16; o > 0; o >>= 1) s += __shfl_xor_sync(0xffffffffu, s, o);
        if (lane == 0) sLog[warp] = s + bi2[0];
    }

    for (int idx = tid; idx < 7 * 1024; idx += 256)
        sU[idx >> 10][idx & 1023] = upd[(long)b * 7168 + idx];
    __syncthreads();

    if (tid == 0) {
        const float capv[7]  = {1.f, 1.f, 1.f, 0.26f, 1.f, 1.f, 0.24f};
        const float freev[7] = {1.f, 1.f, 1.f, 0.f,   1.f, 1.f, 0.f};
        float l[7], mx = -1e30f;
        for (int n = 0; n < 7; n++) { l[n] = sLog[n]; mx = fmaxf(mx, l[n]); }
        float sum = 0.f;
        for (int n = 0; n < 7; n++) { l[n] = expf(l[n] - mx); sum += l[n]; }
        float imp[7];
        for (int n = 0; n < 7; n++) imp[n] = l[n] / sum;
        float capped[7], fm = 0.f, cs = 0.f;
        for (int n = 0; n < 7; n++) {
            capped[n] = fminf(imp[n], capv[n]);
            fm += imp[n] * freev[n];
            cs += capped[n];
        }
        float residual = fmaxf(1.f - cs, 0.f);
        float redis[7], tot = 0.f;
        for (int n = 0; n < 7; n++) {
            float share = (fm > 1e-6f) ? (imp[n] * freev[n] / fmaxf(fm, 1e-6f))
                                       : (freev[n] / 5.f);
            redis[n] = capped[n] + share * residual;
            tot += redis[n];
        }
        float invt = 1.f / fmaxf(tot, 1e-6f);
        for (int n = 0; n < 7; n++) {
            float r = redis[n] * invt;
            simp[n] = r;
            out_imp[b * 7 + n] = r;
        }
    }
    __syncthreads();

    for (int d = tid; d < 1024; d += 256) {
        float f = 0.f;
#pragma unroll
        for (int n = 0; n < 7; n++) f = fmaf(simp[n], sU[n][d], f);
        sF[d] = f;
        out_fused[(long)b * 1024 + d] = f;
    }
    __syncthreads();

    for (int p = warp; p < 36; p += 8) {
        const float *x, *y;
        int n = 0, m = 0;
        if (p < 28) {
            int t = p;
            while (t >= 7 - n) { t -= 7 - n; n++; }
            m = n + t;
            x = sU[n]; y = sU[m];
        } else if (p < 35) {
            n = p - 28; x = sU[n]; y = sF;
        } else {
            x = sF; y = sF;
        }
        float s = 0.f;
        for (int d = lane; d < 1024; d += 32) s = fmaf(x[d], y[d], s);
#pragma unroll
        for (int o = 16; o > 0; o >>= 1) s += __shfl_xor_sync(0xffffffffu, s, o);
        if (lane == 0) {
            if (p < 28)      { sdot[n][m] = s; sdot[m][n] = s; }
            else if (p < 35) { sal[n] = s; }
            else             { sff = s; }
        }
    }
    __syncthreads();

    if (tid == 0) {
        float nrm[7];
        for (int n = 0; n < 7; n++) nrm[n] = sqrtf(sdot[n][n]);
        float nf = sqrtf(sff);
        float edge = 0.f, non = 0.f, al = 0.f;
        for (int n = 0; n < 7; n++) {
            for (int m = 0; m < 7; m++) {
                float cosv = sdot[n][m] / fmaxf(nrm[n] * nrm[m], 1e-8f);
                if (c_adj[n * 7 + m]) edge += 1.f - cosv;
                else                  non  += fmaxf(cosv - 0.35f, 0.f);
            }
            al += 1.f - sal[n] / (fmaxf(nrm[n], 1e-12f) * fmaxf(nf, 1e-12f));
        }
        g_pedge[b] = edge;
        g_pnon[b]  = non;
        g_palign[b] = al;
    }
}

// ---------------- deterministic loss reduction ----------------
__global__ void __launch_bounds__(256) loss_kernel(float* __restrict__ out_phys,
                                                   float* __restrict__ out_align)
{
    __shared__ float se[256], sn[256], sa[256];
    int tid = threadIdx.x;
    float e = 0.f, n = 0.f, a = 0.f;
    for (int b = tid; b < BSZ; b += 256) { e += g_pedge[b]; n += g_pnon[b]; a += g_palign[b]; }
    se[tid] = e; sn[tid] = n; sa[tid] = a;
    __syncthreads();
    for (int o = 128; o > 0; o >>= 1) {
        if (tid < o) { se[tid] += se[tid + o]; sn[tid] += sn[tid + o]; sa[tid] += sa[tid + o]; }
        __syncthreads();
    }
    if (tid == 0) {
        out_phys[0]  = se[0] / 41.f + 0.5f * (sn[0] / 8.f);
        out_align[0] = sa[0] / (1024.f * 7.f);
    }
}

// ---------------- launch ----------------
extern "C" void kernel_launch(void* const* d_in, const int* in_sizes, int n_in,
                              void* d_out, int out_size)
{
    const float* nodes = (const float*)d_in[0];
    const float* Wq  = (const float*)d_in[1];
    const float* bq  = (const float*)d_in[2];
    const float* Wk  = (const float*)d_in[3];
    const float* bk  = (const float*)d_in[4];
    const float* Wv  = (const float*)d_in[5];
    const float* bv  = (const float*)d_in[6];
    const float* We1 = (const float*)d_in[7];
    const float* be1 = (const float*)d_in[8];
    const float* We2 = (const float*)d_in[9];
    const float* be2 = (const float*)d_in[10];
    const float* Wu1 = (const float*)d_in[11];
    const float* bu1 = (const float*)d_in[12];
    const float* Wu2 = (const float*)d_in[13];
    const float* bu2 = (const float*)d_in[14];
    const float* Wi1 = (const float*)d_in[15];
    const float* bi1 = (const float*)d_in[16];
    const float* Wi2 = (const float*)d_in[17];
    const float* bi2 = (const float*)d_in[18];

    float* out = (float*)d_out;
    const long OFF_FUSED = 0;
    const long OFF_UPD   = 1024L * 1024;
    const long OFF_IMP   = OFF_UPD + 7168L * 1024;
    const long OFF_ATTN  = OFF_IMP + 7168;
    const long OFF_PHYS  = OFF_ATTN + 1024L * 49;
    const long OFF_ALIGN = OFF_PHYS + 1;

    float *pqkv, *pcc, *pi1;
    cudaGetSymbolAddress((void**)&pqkv, g_qkv);
    cudaGetSymbolAddress((void**)&pcc,  g_cc);
    cudaGetSymbolAddress((void**)&pi1,  g_i1);

    ushort_t *xh, *xl, *mh, *ml, *uh, *ul, *h1h, *h1l;
    ushort_t *w5h, *w5l, *wch, *wcl, *wu1h, *wu1l, *wu2h, *wu2l, *wi1h, *wi1l;
    cudaGetSymbolAddress((void**)&xh, g_xh);   cudaGetSymbolAddress((void**)&xl, g_xl);
    cudaGetSymbolAddress((void**)&mh, g_mh);   cudaGetSymbolAddress((void**)&ml, g_ml);
    cudaGetSymbolAddress((void**)&uh, g_uh);   cudaGetSymbolAddress((void**)&ul, g_ul);
    cudaGetSymbolAddress((void**)&h1h, g_h1h); cudaGetSymbolAddress((void**)&h1l, g_h1l);
    cudaGetSymbolAddress((void**)&w5h, g_w5h); cudaGetSymbolAddress((void**)&w5l, g_w5l);
    cudaGetSymbolAddress((void**)&wch, g_wch); cudaGetSymbolAddress((void**)&wcl, g_wcl);
    cudaGetSymbolAddress((void**)&wu1h, g_wu1h); cudaGetSymbolAddress((void**)&wu1l, g_wu1l);
    cudaGetSymbolAddress((void**)&wu2h, g_wu2h); cudaGetSymbolAddress((void**)&wu2l, g_wu2l);
    cudaGetSymbolAddress((void**)&wi1h, g_wi1h); cudaGetSymbolAddress((void**)&wi1l, g_wi1l);

    cudaFuncSetAttribute(hmma_gemm, cudaFuncAttributeMaxDynamicSharedMemorySize, HMMA_SMEM);
    cudaFuncSetAttribute(attn_edge_kernel, cudaFuncAttributeMaxDynamicSharedMemorySize, ATTN_SMEM);

    dim3 blk(256);
    dim3 blk512(512);
    dim3 gFusedCC(48, 56);  // 40 main cols + 8 cc cols (cc valid for by<8)
    dim3 gN1(8, 56);        // N=1024/128 x M=7168/128
    const int BIGKA = 1 << 30;

    // job table: all 9 weight transposes (11 z-slices) + nodes conversion
    TJobs jt;
    jt.j[0]  = { Wq,                      w5h + 0L*1024*1024, w5l + 0L*1024*1024, 1024, 0 };
    jt.j[1]  = { Wk,                      w5h + 1L*1024*1024, w5l + 1L*1024*1024, 1024, 0 };
    jt.j[2]  = { Wv,                      w5h + 2L*1024*1024, w5l + 2L*1024*1024, 1024, 0 };
    jt.j[3]  = { We1,                     w5h + 3L*1024*1024, w5l + 3L*1024*1024, 1024, 0 };
    jt.j[4]  = { We1 + 1024*1024,         w5h + 4L*1024*1024, w5l + 4L*1024*1024, 1024, 0 };
    jt.j[5]  = { We1 + 2*1024*1024,       wch,  wcl,  1024, 0 };
    jt.j[6]  = { Wu1,                     wu1h, wu1l, 2048, 0 };
    jt.j[7]  = { Wu1,                     wu1h, wu1l, 2048, 1024 };
    jt.j[8]  = { Wu2,                     wu2h, wu2l, 1024, 0 };
    jt.j[9]  = { Wi1,                     wi1h, wi1l, 2048, 0 };
    jt.j[10] = { Wi1,                     wi1h, wi1l, 2048, 1024 };

    prep_all<<<PREP_BLOCKS + CONV_BLOCKS, blk>>>(jt, nodes, xh, xl);                 // 0

    // fused [q|k|v|la|rb] = nodes @ [Wq|Wk|Wv|Wa|Wb]  +  cc side-job in same grid   // 1
    hmma_gemm<<<gFusedCC, blk512, HMMA_SMEM>>>(xh, xl, nullptr, nullptr, BIGKA, 0, 1024,
                                               w5h, w5l, 1024, 1024,
                                               bq, bk, bv, nullptr, pqkv, 5120,
                                               nullptr, nullptr, 0, 0,
                                               40,
                                               xh + 6 * 1024, xl + 6 * 1024, 7 * 1024,
                                               wch, wcl, pcc);

    attn_edge_kernel<<<1024, blk512, ATTN_SMEM>>>(pqkv, pcc, be1, We2, be2,
                                                  out + OFF_ATTN, mh, ml);           // 2

    // h1 = gelu([nodes|msg] @ Wu1 + bu1), N=1024, K=2048 -> bf16 split only         // 3
    hmma_gemm<<<gN1, blk512, HMMA_SMEM>>>(xh, xl, mh, ml, 1024, 0, 1024,
                                          wu1h, wu1l, 2048, 2048,
                                          bu1, nullptr, nullptr, nullptr, nullptr, 0,
                                          h1h, h1l, 1024, 1,
                                          1 << 20, nullptr, nullptr, 0, nullptr, nullptr, nullptr);
    // updated = h1 @ Wu2 + bu2 + nodes, N=1024, K=1024 -> fp32 out + bf16 split     // 4
    hmma_gemm<<<gN1, blk512, HMMA_SMEM>>>(h1h, h1l, nullptr, nullptr, BIGKA, 0, 1024,
                                          wu2h, wu2l, 1024, 1024,
                                          bu2, nullptr, nullptr, nodes, out + OFF_UPD, 1024,
                                          uh, ul, 1024, 0,
                                          1 << 20, nullptr, nullptr, 0, nullptr, nullptr, nullptr);
    // i1 = gelu([updated|gq] @ Wi1 + bi1), N=1024, K=2048; gq via row remap         // 5
    hmma_gemm<<<gN1, blk512, HMMA_SMEM>>>(uh, ul, uh, ul, 1024, 1, 1024,
                                          wi1h, wi1l, 2048, 2048,
                                          bi1, nullptr, nullptr, nullptr, pi1, 1024,
                                          nullptr, nullptr, 0, 1,
                                          1 << 20, nullptr, nullptr, 0, nullptr, nullptr, nullptr);

    finalize_kernel<<<1024, blk>>>(out + OFF_UPD, pi1, Wi2, bi2,
                                   out + OFF_FUSED, out + OFF_IMP);                  // 6
    loss_kernel<<<1, blk>>>(out + OFF_PHYS, out + OFF_ALIGN);                        // 7
}

// round 16
// speedup vs baseline: 1.5385x; 1.5385x over previous
#include <cuda_runtime.h>
#include <cuda_bf16.h>
#include <math.h>

// Problem constants
#define BSZ 1024
#define NN  7
#define DD  1024
#define BN  (BSZ*NN)   // 7168

typedef unsigned short ushort_t;

// ---------------- fp32 scratch ----------------
__device__ float g_qkv[BN*5120];     // [q|k|v|la|rb]
__device__ float g_cc[BSZ*DD];
__device__ float g_i1[BN*DD];
__device__ float g_pedge[BSZ];
__device__ float g_pnon[BSZ];
__device__ float g_palign[BSZ];

// ---------------- bf16 (ushort) split scratch, ld=1024 ----------------
__device__ ushort_t g_xh[BN*DD],  g_xl[BN*DD];    // nodes
__device__ ushort_t g_mh[BN*DD],  g_ml[BN*DD];    // messages
__device__ ushort_t g_uh[BN*DD],  g_ul[BN*DD];    // updated
__device__ ushort_t g_h1h[BN*DD], g_h1l[BN*DD];   // gelu hidden
// transposed weights, [N, K] K-major
__device__ ushort_t g_w5h[5120*DD], g_w5l[5120*DD];   // [Wq|Wk|Wv|Wa|Wb]
__device__ ushort_t g_wch[DD*DD],   g_wcl[DD*DD];
__device__ ushort_t g_wu1h[DD*2048], g_wu1l[DD*2048];
__device__ ushort_t g_wu2h[DD*DD],   g_wu2l[DD*DD];
__device__ ushort_t g_wi1h[DD*2048], g_wi1l[DD*2048];

__constant__ int c_adj[49] = {
    1,1,0,0,1,1,1,
    1,1,1,1,1,1,1,
    0,1,1,0,1,0,1,
    0,1,0,1,1,1,1,
    1,1,1,1,1,1,1,
    1,1,0,1,1,1,1,
    1,1,1,1,1,1,1
};
// unmasked (n,m) pairs, packed n*7+m (41 entries)
__constant__ unsigned char c_pairs[41] = {
    0,1,4,5,6,
    7,8,9,10,11,12,13,
    15,16,18,20,
    22,24,25,26,27,
    28,29,30,31,32,33,34,
    35,36,38,39,40,41,
    42,43,44,45,46,47,48
};

__device__ __forceinline__ float gelu_f(float x) { return x * normcdff(x); }

// ---------------- helpers ----------------
__device__ __forceinline__ unsigned smem_u32(const void* p) {
    unsigned a;
    asm("{ .reg .u64 t; cvta.to.shared.u64 t, %1; cvt.u32.u64 %0, t; }" : "=r"(a) : "l"(p));
    return a;
}
#define SMEM_SWIZZLE_128B(x) ((x) ^ (((x) >> 3) & 0x70))

#define CP_ASYNC16(s, g) \
    asm volatile("cp.async.cg.shared.global [%0], [%1], 16;" :: "r"(s), "l"(g) : "memory")
#define CP_COMMIT() asm volatile("cp.async.commit_group;" ::: "memory")
#define CP_WAIT0()  asm volatile("cp.async.wait_group 0;" ::: "memory")

#define LDSM4(r, a) \
    asm volatile("ldmatrix.sync.aligned.m8n8.x4.shared.b16 {%0,%1,%2,%3}, [%4];" \
        : "=r"((r)[0]), "=r"((r)[1]), "=r"((r)[2]), "=r"((r)[3]) : "r"(a))

#define MMA16816(d, a, b) \
    asm volatile("mma.sync.aligned.m16n8k16.row.col.f32.bf16.bf16.f32 " \
        "{%0,%1,%2,%3}, {%4,%5,%6,%7}, {%8,%9}, {%0,%1,%2,%3};" \
        : "+f"((d)[0]), "+f"((d)[1]), "+f"((d)[2]), "+f"((d)[3]) \
        : "r"((a)[0]), "r"((a)[1]), "r"((a)[2]), "r"((a)[3]), "r"((b)[0]), "r"((b)[1]))

// ---------------- bf16 split ----------------
__device__ __forceinline__ void split_bf16(float v, ushort_t& h, ushort_t& l) {
    __nv_bfloat16 hb = __float2bfloat16(v);
    __nv_bfloat16 lb = __float2bfloat16(v - __bfloat162float(hb));
    h = *reinterpret_cast<ushort_t*>(&hb);
    l = *reinterpret_cast<ushort_t*>(&lb);
}

// ---------------- one kernel: weight transposes + nodes convert (vectorized) ----------------
struct TJob { const float* W; ushort_t* th; ushort_t* tl; int Kdst; int k0off; };
struct TJobs { TJob j[11]; };
#define PREP_BLOCKS 11264   // 11 jobs x 32x32 blocks
#define CONV_BLOCKS 7168    // 7168*1024 elems / (256 threads * 4 elems)

__global__ void __launch_bounds__(256) prep_all(
    TJobs jobs, const float* __restrict__ nodes,
    ushort_t* __restrict__ dh, ushort_t* __restrict__ dl)
{
    __shared__ float t[32][33];
    int bid = blockIdx.x;
    if (bid < PREP_BLOCKS) {
        TJob job = jobs.j[bid >> 10];
        int w = bid & 1023;
        int n0 = (w & 31) * 32, k0 = (w >> 5) * 32 + job.k0off;
        int tx = threadIdx.x & 31, ty = threadIdx.x >> 5;
#pragma unroll
        for (int i = 0; i < 32; i += 8)
            t[ty + i][tx] = job.W[(long)(k0 + ty + i) * 1024 + n0 + tx];
        __syncthreads();
#pragma unroll
        for (int i = 0; i < 32; i += 8) {
            float v = t[tx][ty + i];
            long o = (long)(n0 + ty + i) * job.Kdst + k0 + tx;
            ushort_t h, l; split_bf16(v, h, l);
            job.th[o] = h; job.tl[o] = l;
        }
    } else {
        long i4 = (long)(bid - PREP_BLOCKS) * 1024 + (long)threadIdx.x * 4;
        float4 v = *(const float4*)(nodes + i4);
        ushort4 h4, l4;
        split_bf16(v.x, h4.x, l4.x);
        split_bf16(v.y, h4.y, l4.y);
        split_bf16(v.z, h4.z, l4.z);
        split_bf16(v.w, h4.w, l4.w);
        *(ushort4*)(dh + i4) = h4;
        *(ushort4*)(dl + i4) = l4;
    }
}

// ---------------- HMMA split-bf16 GEMM (R13 champion, unchanged) ----------------
// CTA 128x128, 512 threads: 16 warps (4x4) of 32x32 warp tiles.
// K-chunk 64, cp.async double buffer (2 stages, 128KB smem).
#define TILE_B   16384                      // 128 rows x 128 bytes
#define STAGE_B  (4*TILE_B)                 // Ah, Al, Bh, Bl = 65536
#define HMMA_SMEM (2*STAGE_B)               // 131072

__device__ __forceinline__ void load_tile_async(
    unsigned dst, const ushort_t* __restrict__ src, long ld, long r0, int kc, int remap)
{
    int t = threadIdx.x;          // 0..511
    int rr = t >> 3;              // 0..63
    int o  = (t & 7) << 4;        // 16B offset in 128B row
#pragma unroll
    for (int p = 0; p < 2; p++) {
        int r = rr + p * 64;
        long gr = r0 + r;
        if (remap) gr = (gr / 7) * 7 + 6;
        const void* g = (const void*)(src + gr * ld + kc + (o >> 1));
        unsigned s = dst + SMEM_SWIZZLE_128B(r * 128 + o);
        CP_ASYNC16(s, g);
    }
}

__device__ __forceinline__ void load_stage(
    unsigned base,
    const ushort_t* a1h, const ushort_t* a1l,
    const ushort_t* a2h, const ushort_t* a2l,
    int KA, int remap2, long lda,
    const ushort_t* b_h, const ushort_t* b_l, long ldb,
    long row0, int col0, int kc)
{
    const ushort_t *sh = a1h, *sl = a1l; int kloc = kc, rm = 0;
    if (kc >= KA) { sh = a2h; sl = a2l; kloc = kc - KA; rm = remap2; }
    load_tile_async(base + 0 * TILE_B, sh, lda, row0, kloc, rm);
    load_tile_async(base + 1 * TILE_B, sl, lda, row0, kloc, rm);
    load_tile_async(base + 2 * TILE_B, b_h, ldb, col0, kc, 0);
    load_tile_async(base + 3 * TILE_B, b_l, ldb, col0, kc, 0);
    CP_COMMIT();
}

__global__ void __launch_bounds__(512, 1) hmma_gemm(
    const ushort_t* __restrict__ a1h_, const ushort_t* __restrict__ a1l_,
    const ushort_t* __restrict__ a2h_, const ushort_t* __restrict__ a2l_,
    int KA_, int remap2_, long lda_,
    const ushort_t* __restrict__ b_h_, const ushort_t* __restrict__ b_l_, long ldb_,
    int K_,
    const float* __restrict__ bias_,
    const float* __restrict__ biasB_, const float* __restrict__ biasC_,
    const float* __restrict__ resid_,
    float* __restrict__ C_, int ldc_,
    ushort_t* __restrict__ o_h_, ushort_t* __restrict__ o_l_, int ldo_,
    int dogelu_,
    int mainGX,
    const ushort_t* __restrict__ ccAh, const ushort_t* __restrict__ ccAl, long cclda,
    const ushort_t* __restrict__ ccBh, const ushort_t* __restrict__ ccBl,
    float* __restrict__ ccC)
{
    // job selection
    const ushort_t *a1h = a1h_, *a1l = a1l_, *a2h = a2h_, *a2l = a2l_;
    const ushort_t *b_h = b_h_, *b_l = b_l_;
    const float *bias = bias_, *biasB = biasB_, *biasC = biasC_, *resid = resid_;
    float* C = C_;
    ushort_t *o_h = o_h_, *o_l = o_l_;
    int KA = KA_, remap2 = remap2_, K = K_, ldc = ldc_, ldo = ldo_, dogelu = dogelu_;
    long lda = lda_, ldb = ldb_;
    int bx = blockIdx.x, by = blockIdx.y;
    if (bx >= mainGX) {
        if (by >= 8) return;                 // cc output is only 1024 rows
        bx -= mainGX;
        a1h = ccAh; a1l = ccAl; a2h = nullptr; a2l = nullptr;
        KA = 1 << 30; remap2 = 0; lda = cclda;
        b_h = ccBh; b_l = ccBl; ldb = 1024; K = 1024;
        bias = nullptr; biasB = nullptr; biasC = nullptr; resid = nullptr;
        C = ccC; ldc = 1024; o_h = nullptr; o_l = nullptr; dogelu = 0;
    }

    extern __shared__ char smem[];
    unsigned sb = smem_u32(smem);
    const int tid = threadIdx.x;
    const int wid = tid >> 5, lane = tid & 31;
    const int wm = wid & 3, wn = wid >> 2;    // 4x4 warps, 32x32 each
    const long row0 = (long)by * 128;
    const int  col0 = bx * 128;
    const int NCH = K >> 6;

    float acc[2][4][4];
#pragma unroll
    for (int i = 0; i < 2; i++)
#pragma unroll
        for (int j = 0; j < 4; j++)
#pragma unroll
            for (int e = 0; e < 4; e++) acc[i][j][e] = 0.f;

    const int aRow  = wm * 32 + (lane & 15);
    const int aKoff = (lane >> 4) << 4;
    const int bRow0 = wn * 32 + (lane & 7) + ((lane >> 4) << 3);
    const int bKoff = ((lane >> 3) & 1) << 4;

    // prologue: chunk 0 -> stage 0
    load_stage(sb, a1h, a1l, a2h, a2l, KA, remap2, lda, b_h, b_l, ldb, row0, col0, 0);
    CP_WAIT0();
    __syncthreads();

    for (int c = 0; c < NCH; c++) {
        int s = c & 1;
        if (c + 1 < NCH)
            load_stage(sb + (s ^ 1) * STAGE_B, a1h, a1l, a2h, a2l, KA, remap2, lda,
                       b_h, b_l, ldb, row0, col0, (c + 1) << 6);
        unsigned stage = sb + s * STAGE_B;
#pragma unroll
        for (int k16 = 0; k16 < 4; k16++) {
            unsigned ah[2][4], al[2][4];
#pragma unroll
            for (int mt = 0; mt < 2; mt++) {
                unsigned off = (unsigned)((aRow + mt * 16) * 128 + k16 * 32 + aKoff);
                off = SMEM_SWIZZLE_128B(off);
                LDSM4(ah[mt], stage + 0 * TILE_B + off);
                LDSM4(al[mt], stage + 1 * TILE_B + off);
            }
            unsigned bhf[4][2], blf[4][2];
#pragma unroll
            for (int np = 0; np < 2; np++) {
                unsigned off = (unsigned)((bRow0 + np * 16) * 128 + k16 * 32 + bKoff);
                off = SMEM_SWIZZLE_128B(off);
                unsigned r[4];
                LDSM4(r, stage + 2 * TILE_B + off);
                bhf[2*np][0] = r[0]; bhf[2*np][1] = r[1];
                bhf[2*np+1][0] = r[2]; bhf[2*np+1][1] = r[3];
                LDSM4(r, stage + 3 * TILE_B + off);
                blf[2*np][0] = r[0]; blf[2*np][1] = r[1];
                blf[2*np+1][0] = r[2]; blf[2*np+1][1] = r[3];
            }
            // term-outer: 8 independent MMAs between accumulator reuses
#pragma unroll
            for (int mt = 0; mt < 2; mt++)
#pragma unroll
                for (int nt = 0; nt < 4; nt++)
                    MMA16816(acc[mt][nt], ah[mt], bhf[nt]);
#pragma unroll
            for (int mt = 0; mt < 2; mt++)
#pragma unroll
                for (int nt = 0; nt < 4; nt++)
                    MMA16816(acc[mt][nt], ah[mt], blf[nt]);
#pragma unroll
            for (int mt = 0; mt < 2; mt++)
#pragma unroll
                for (int nt = 0; nt < 4; nt++)
                    MMA16816(acc[mt][nt], al[mt], bhf[nt]);
        }
        if (c + 1 < NCH) CP_WAIT0();
        __syncthreads();
    }

    // epilogue: rows wm*32+mt*16+(lane>>2)+{0,8}, cols wn*32+nt*8+(lane&3)*2+{0,1}
#pragma unroll
    for (int mt = 0; mt < 2; mt++)
#pragma unroll
        for (int h = 0; h < 2; h++) {
            long r = row0 + wm * 32 + mt * 16 + (lane >> 2) + h * 8;
#pragma unroll
            for (int nt = 0; nt < 4; nt++)
#pragma unroll
                for (int e = 0; e < 2; e++) {
                    int col = col0 + wn * 32 + nt * 8 + (lane & 3) * 2 + e;
                    float v = acc[mt][nt][h * 2 + e];
                    if (biasB) {
                        int seg = col >> 10;
                        float bv = 0.f;
                        if (seg == 0)      bv = bias[col];
                        else if (seg == 1) bv = biasB[col - 1024];
                        else if (seg == 2) bv = biasC[col - 2048];
                        v += bv;
                    } else if (bias) {
                        v += bias[col];
                    }
                    if (resid) v += resid[r * 1024 + col];
                    if (dogelu) v = gelu_f(v);
                    if (C) C[r * (long)ldc + col] = v;
                    if (o_h) {
                        ushort_t hh, ll; split_bf16(v, hh, ll);
                        o_h[r * (long)ldo + col] = hh;
                        o_l[r * (long)ldo + col] = ll;
                    }
                }
        }
}

// ---------------- per-batch attention + edge MLP + softmax + messages ----------------
// R13 version: 512 threads, static smem, multi-CTA/SM occupancy.
__global__ void __launch_bounds__(512) attn_edge_kernel(
    const float* __restrict__ qkv, const float* __restrict__ cc,
    const float* __restrict__ be1, const float* __restrict__ We2, const float* __restrict__ be2,
    float* __restrict__ attn_out,
    ushort_t* __restrict__ mh, ushort_t* __restrict__ ml)
{
    const int b = blockIdx.x;
    const int tid = threadIdx.x;
    const int warp = tid >> 5, lane = tid & 31;
    __shared__ float sRB[7][1024];
    __shared__ float sW2[1024];
    __shared__ float sP[7][7];

    if (tid < 49) sP[tid / 7][tid % 7] = -10000.f;
    for (int idx = tid; idx < 7 * 1024; idx += 512) {
        int m = idx >> 10, d = idx & 1023;
        sRB[m][d] = qkv[((long)b * 7 + m) * 5120 + 4096 + d] + cc[(long)b * 1024 + d] + be1[d];
    }
    for (int d = tid; d < 1024; d += 512) sW2[d] = We2[d];
    __syncthreads();

    for (int p = warp; p < 41; p += 16) {
        int pm = c_pairs[p];
        int n = pm / 7, m = pm % 7;
        const float* qp  = qkv + ((long)b * 7 + n) * 5120;
        const float* kp  = qkv + ((long)b * 7 + m) * 5120 + 1024;
        const float* lap = qkv + ((long)b * 7 + n) * 5120 + 3072;
        float s = 0.f, e = 0.f;
        for (int d = lane; d < 1024; d += 32) {
            s = fmaf(qp[d], kp[d], s);
            float x = lap[d] + sRB[m][d];
            e = fmaf(gelu_f(x), sW2[d], e);
        }
#pragma unroll
        for (int o = 16; o > 0; o >>= 1) {
            s += __shfl_xor_sync(0xffffffffu, s, o);
            e += __shfl_xor_sync(0xffffffffu, e, o);
        }
        if (lane == 0)
            sP[n][m] = s * (1.f / 32.f) + e + be2[0];
    }
    __syncthreads();
    if (tid < 7) {
        int n = tid;
        float mx = -1e30f;
        for (int m = 0; m < 7; m++) mx = fmaxf(mx, sP[n][m]);
        float pv[7], sum = 0.f;
        for (int m = 0; m < 7; m++) { pv[m] = expf(sP[n][m] - mx); sum += pv[m]; }
        float inv = 1.f / sum;
        for (int m = 0; m < 7; m++) {
            float a = pv[m] * inv;
            sP[n][m] = a;
            attn_out[(long)b * 49 + n * 7 + m] = a;
        }
    }
    __syncthreads();
    for (int idx = tid; idx < 7 * 1024; idx += 512) {
        int n = idx >> 10, d = idx & 1023;
        float s = 0.f;
#pragma unroll
        for (int m = 0; m < 7; m++)
            s = fmaf(sP[n][m], qkv[((long)b * 7 + m) * 5120 + 2048 + d], s);
        ushort_t h, l; split_bf16(s, h, l);
        long o = ((long)b * 7 + n) * 1024 + d;
        mh[o] = h; ml[o] = l;
    }
}

// ---------------- per-batch finalize (computes importance logits inline) ----------------
__global__ void __launch_bounds__(256) finalize_kernel(
    const float* __restrict__ upd, const float* __restrict__ i1,
    const float* __restrict__ Wi2, const float* __restrict__ bi2,
    float* __restrict__ out_fused, float* __restrict__ out_imp)
{
    const int b = blockIdx.x;
    const int tid = threadIdx.x;
    const int warp = tid >> 5, lane = tid & 31;
    __shared__ float sU[7][1024];
    __shared__ float sF[1024];
    __shared__ float sLog[7];
    __shared__ float simp[7];
    __shared__ float sdot[7][7];
    __shared__ float sal[7];
    __shared__ float sff;

    if (warp < 7) {
        const float* p = i1 + ((long)b * 7 + warp) * 1024;
        float s = 0.f;
        for (int d = lane; d < 1024; d += 32) s = fmaf(p[d], Wi2[d], s);
#pragma unroll
        for (int o = 16; o > 0; o >>= 1) s += __shfl_xor_sync(0xffffffffu, s, o);
        if (lane == 0) sLog[warp] = s + bi2[0];
    }

    for (int idx = tid; idx < 7 * 1024; idx += 256)
        sU[idx >> 10][idx & 1023] = upd[(long)b * 7168 + idx];
    __syncthreads();

    if (tid == 0) {
        const float capv[7]  = {1.f, 1.f, 1.f, 0.26f, 1.f, 1.f, 0.24f};
        const float freev[7] = {1.f, 1.f, 1.f, 0.f,   1.f, 1.f, 0.f};
        float l[7], mx = -1e30f;
        for (int n = 0; n < 7; n++) { l[n] = sLog[n]; mx = fmaxf(mx, l[n]); }
        float sum = 0.f;
        for (int n = 0; n < 7; n++) { l[n] = expf(l[n] - mx); sum += l[n]; }
        float imp[7];
        for (int n = 0; n < 7; n++) imp[n] = l[n] / sum;
        float capped[7], fm = 0.f, cs = 0.f;
        for (int n = 0; n < 7; n++) {
            capped[n] = fminf(imp[n], capv[n]);
            fm += imp[n] * freev[n];
            cs += capped[n];
        }
        float residual = fmaxf(1.f - cs, 0.f);
        float redis[7], tot = 0.f;
        for (int n = 0; n < 7; n++) {
            float share = (fm > 1e-6f) ? (imp[n] * freev[n] / fmaxf(fm, 1e-6f))
                                       : (freev[n] / 5.f);
            redis[n] = capped[n] + share * residual;
            tot += redis[n];
        }
        float invt = 1.f / fmaxf(tot, 1e-6f);
        for (int n = 0; n < 7; n++) {
            float r = redis[n] * invt;
            simp[n] = r;
            out_imp[b * 7 + n] = r;
        }
    }
    __syncthreads();

    for (int d = tid; d < 1024; d += 256) {
        float f = 0.f;
#pragma unroll
        for (int n = 0; n < 7; n++) f = fmaf(simp[n], sU[n][d], f);
        sF[d] = f;
        out_fused[(long)b * 1024 + d] = f;
    }
    __syncthreads();

    for (int p = warp; p < 36; p += 8) {
        const float *x, *y;
        int n = 0, m = 0;
        if (p < 28) {
            int t = p;
            while (t >= 7 - n) { t -= 7 - n; n++; }
            m = n + t;
            x = sU[n]; y = sU[m];
        } else if (p < 35) {
            n = p - 28; x = sU[n]; y = sF;
        } else {
            x = sF; y = sF;
        }
        float s = 0.f;
        for (int d = lane; d < 1024; d += 32) s = fmaf(x[d], y[d], s);
#pragma unroll
        for (int o = 16; o > 0; o >>= 1) s += __shfl_xor_sync(0xffffffffu, s, o);
        if (lane == 0) {
            if (p < 28)      { sdot[n][m] = s; sdot[m][n] = s; }
            else if (p < 35) { sal[n] = s; }
            else             { sff = s; }
        }
    }
    __syncthreads();

    if (tid == 0) {
        float nrm[7];
        for (int n = 0; n < 7; n++) nrm[n] = sqrtf(sdot[n][n]);
        float nf = sqrtf(sff);
        float edge = 0.f, non = 0.f, al = 0.f;
        for (int n = 0; n < 7; n++) {
            for (int m = 0; m < 7; m++) {
                float cosv = sdot[n][m] / fmaxf(nrm[n] * nrm[m], 1e-8f);
                if (c_adj[n * 7 + m]) edge += 1.f - cosv;
                else                  non  += fmaxf(cosv - 0.35f, 0.f);
            }
            al += 1.f - sal[n] / (fmaxf(nrm[n], 1e-12f) * fmaxf(nf, 1e-12f));
        }
        g_pedge[b] = edge;
        g_pnon[b]  = non;
        g_palign[b] = al;
    }
}

// ---------------- deterministic loss reduction ----------------
__global__ void __launch_bounds__(256) loss_kernel(float* __restrict__ out_phys,
                                                   float* __restrict__ out_align)
{
    __shared__ float se[256], sn[256], sa[256];
    int tid = threadIdx.x;
    float e = 0.f, n = 0.f, a = 0.f;
    for (int b = tid; b < BSZ; b += 256) { e += g_pedge[b]; n += g_pnon[b]; a += g_palign[b]; }
    se[tid] = e; sn[tid] = n; sa[tid] = a;
    __syncthreads();
    for (int o = 128; o > 0; o >>= 1) {
        if (tid < o) { se[tid] += se[tid + o]; sn[tid] += sn[tid + o]; sa[tid] += sa[tid + o]; }
        __syncthreads();
    }
    if (tid == 0) {
        out_phys[0]  = se[0] / 41.f + 0.5f * (sn[0] / 8.f);
        out_align[0] = sa[0] / (1024.f * 7.f);
    }
}

// ---------------- launch ----------------
extern "C" void kernel_launch(void* const* d_in, const int* in_sizes, int n_in,
                              void* d_out, int out_size)
{
    const float* nodes = (const float*)d_in[0];
    const float* Wq  = (const float*)d_in[1];
    const float* bq  = (const float*)d_in[2];
    const float* Wk  = (const float*)d_in[3];
    const float* bk  = (const float*)d_in[4];
    const float* Wv  = (const float*)d_in[5];
    const float* bv  = (const float*)d_in[6];
    const float* We1 = (const float*)d_in[7];
    const float* be1 = (const float*)d_in[8];
    const float* We2 = (const float*)d_in[9];
    const float* be2 = (const float*)d_in[10];
    const float* Wu1 = (const float*)d_in[11];
    const float* bu1 = (const float*)d_in[12];
    const float* Wu2 = (const float*)d_in[13];
    const float* bu2 = (const float*)d_in[14];
    const float* Wi1 = (const float*)d_in[15];
    const float* bi1 = (const float*)d_in[16];
    const float* Wi2 = (const float*)d_in[17];
    const float* bi2 = (const float*)d_in[18];

    float* out = (float*)d_out;
    const long OFF_FUSED = 0;
    const long OFF_UPD   = 1024L * 1024;
    const long OFF_IMP   = OFF_UPD + 7168L * 1024;
    const long OFF_ATTN  = OFF_IMP + 7168;
    const long OFF_PHYS  = OFF_ATTN + 1024L * 49;
    const long OFF_ALIGN = OFF_PHYS + 1;

    float *pqkv, *pcc, *pi1;
    cudaGetSymbolAddress((void**)&pqkv, g_qkv);
    cudaGetSymbolAddress((void**)&pcc,  g_cc);
    cudaGetSymbolAddress((void**)&pi1,  g_i1);

    ushort_t *xh, *xl, *mh, *ml, *uh, *ul, *h1h, *h1l;
    ushort_t *w5h, *w5l, *wch, *wcl, *wu1h, *wu1l, *wu2h, *wu2l, *wi1h, *wi1l;
    cudaGetSymbolAddress((void**)&xh, g_xh);   cudaGetSymbolAddress((void**)&xl, g_xl);
    cudaGetSymbolAddress((void**)&mh, g_mh);   cudaGetSymbolAddress((void**)&ml, g_ml);
    cudaGetSymbolAddress((void**)&uh, g_uh);   cudaGetSymbolAddress((void**)&ul, g_ul);
    cudaGetSymbolAddress((void**)&h1h, g_h1h); cudaGetSymbolAddress((void**)&h1l, g_h1l);
    cudaGetSymbolAddress((void**)&w5h, g_w5h); cudaGetSymbolAddress((void**)&w5l, g_w5l);
    cudaGetSymbolAddress((void**)&wch, g_wch); cudaGetSymbolAddress((void**)&wcl, g_wcl);
    cudaGetSymbolAddress((void**)&wu1h, g_wu1h); cudaGetSymbolAddress((void**)&wu1l, g_wu1l);
    cudaGetSymbolAddress((void**)&wu2h, g_wu2h); cudaGetSymbolAddress((void**)&wu2l, g_wu2l);
    cudaGetSymbolAddress((void**)&wi1h, g_wi1h); cudaGetSymbolAddress((void**)&wi1l, g_wi1l);

    cudaFuncSetAttribute(hmma_gemm, cudaFuncAttributeMaxDynamicSharedMemorySize, HMMA_SMEM);

    dim3 blk(256);
    dim3 blk512(512);
    dim3 gFusedCC(48, 56);  // 40 main cols + 8 cc cols (cc valid for by<8)
    dim3 gN1(8, 56);        // N=1024/128 x M=7168/128
    const int BIGKA = 1 << 30;

    // job table: all 9 weight transposes (11 z-slices) + nodes conversion
    TJobs jt;
    jt.j[0]  = { Wq,                      w5h + 0L*1024*1024, w5l + 0L*1024*1024, 1024, 0 };
    jt.j[1]  = { Wk,                      w5h + 1L*1024*1024, w5l + 1L*1024*1024, 1024, 0 };
    jt.j[2]  = { Wv,                      w5h + 2L*1024*1024, w5l + 2L*1024*1024, 1024, 0 };
    jt.j[3]  = { We1,                     w5h + 3L*1024*1024, w5l + 3L*1024*1024, 1024, 0 };
    jt.j[4]  = { We1 + 1024*1024,         w5h + 4L*1024*1024, w5l + 4L*1024*1024, 1024, 0 };
    jt.j[5]  = { We1 + 2*1024*1024,       wch,  wcl,  1024, 0 };
    jt.j[6]  = { Wu1,                     wu1h, wu1l, 2048, 0 };
    jt.j[7]  = { Wu1,                     wu1h, wu1l, 2048, 1024 };
    jt.j[8]  = { Wu2,                     wu2h, wu2l, 1024, 0 };
    jt.j[9]  = { Wi1,                     wi1h, wi1l, 2048, 0 };
    jt.j[10] = { Wi1,                     wi1h, wi1l, 2048, 1024 };

    prep_all<<<PREP_BLOCKS + CONV_BLOCKS, blk>>>(jt, nodes, xh, xl);                 // 0

    // fused [q|k|v|la|rb] = nodes @ [Wq|Wk|Wv|Wa|Wb]  +  cc side-job in same grid   // 1
    hmma_gemm<<<gFusedCC, blk512, HMMA_SMEM>>>(xh, xl, nullptr, nullptr, BIGKA, 0, 1024,
                                               w5h, w5l, 1024, 1024,
                                               bq, bk, bv, nullptr, pqkv, 5120,
                                               nullptr, nullptr, 0, 0,
                                               40,
                                               xh + 6 * 1024, xl + 6 * 1024, 7 * 1024,
                                               wch, wcl, pcc);

    attn_edge_kernel<<<1024, blk512>>>(pqkv, pcc, be1, We2, be2, out + OFF_ATTN, mh, ml); // 2

    // h1 = gelu([nodes|msg] @ Wu1 + bu1), N=1024, K=2048 -> bf16 split only         // 3
    hmma_gemm<<<gN1, blk512, HMMA_SMEM>>>(xh, xl, mh, ml, 1024, 0, 1024,
                                          wu1h, wu1l, 2048, 2048,
                                          bu1, nullptr, nullptr, nullptr, nullptr, 0,
                                          h1h, h1l, 1024, 1,
                                          1 << 20, nullptr, nullptr, 0, nullptr, nullptr, nullptr);
    // updated = h1 @ Wu2 + bu2 + nodes, N=1024, K=1024 -> fp32 out + bf16 split     // 4
    hmma_gemm<<<gN1, blk512, HMMA_SMEM>>>(h1h, h1l, nullptr, nullptr, BIGKA, 0, 1024,
                                          wu2h, wu2l, 1024, 1024,
                                          bu2, nullptr, nullptr, nodes, out + OFF_UPD, 1024,
                                          uh, ul, 1024, 0,
                                          1 << 20, nullptr, nullptr, 0, nullptr, nullptr, nullptr);
    // i1 = gelu([updated|gq] @ Wi1 + bi1), N=1024, K=2048; gq via row remap         // 5
    hmma_gemm<<<gN1, blk512, HMMA_SMEM>>>(uh, ul, uh, ul, 1024, 1, 1024,
                                          wi1h, wi1l, 2048, 2048,
                                          bi1, nullptr, nullptr, nullptr, pi1, 1024,
                                          nullptr, nullptr, 0, 1,
                                          1 << 20, nullptr, nullptr, 0, nullptr, nullptr, nullptr);

    finalize_kernel<<<1024, blk>>>(out + OFF_UPD, pi1, Wi2, bi2,
                                   out + OFF_FUSED, out + OFF_IMP);                  // 6
    loss_kernel<<<1, blk>>>(out + OFF_PHYS, out + OFF_ALIGN);                        // 7
}